// round 6
// baseline (speedup 1.0000x reference)
#include <cuda_runtime.h>
#include <cstdint>

// ---------------------------------------------------------------------------
// Swin WindowAttention, fused per-window TF32 mma.sync kernel, round 6.
// Round-5 design with the VT/P stride overflow fixed (SVT,SP: 40/56 -> 72).
// 1024 threads. Register-fused attention (logits+softmax in regs, per-warp
// P scratch, no block barrier inside attention), ping-pong weight staging,
// warp-specialized proj_w prefetch, direct STG epilogue.
// ---------------------------------------------------------------------------

namespace {
constexpr int NTOK  = 49;
constexpr int CDIM  = 128;
constexpr int NHEAD = 4;
constexpr int TC3   = 384;
constexpr int MAXW  = 64;
constexpr int S136  = 136;   // operand stride (%32==8)
constexpr int SVT   = 72;    // V-transposed stride (%32==8, >= 56 packed tokens)
constexpr int SP    = 72;    // per-warp P scratch stride (%32==8, >= 56)

// buffer layout (floats)
constexpr int OFF_Q  = 0;                    // [64][136]
constexpr int OFF_K  = OFF_Q  + 64 * S136;   // [64][136]
constexpr int OFF_VT = OFF_K  + 64 * S136;   // [128][72]
constexpr int OFF_XS = OFF_VT + 128 * SVT;   // [64][136] x, then attn-out
constexpr int OFF_WB = OFF_XS + 64 * S136;   // W ping-pong (17408) / P scratch (18432)
constexpr int WBREG  = 16 * 16 * SP;         // 18432 >= 2*64*S136
constexpr int SMEMF  = OFF_WB + WBREG;       // 53760 floats = 215040 B
}

__device__ float g_wqkv_t[TC3 * CDIM];             // [n=384][pk(k=128)]
__device__ float g_wproj_t[CDIM * CDIM];           // [n=128][pk(k=128)]
__device__ float g_rm[MAXW * NHEAD * 64 * 64];     // rpb+mask, padded with -1e30

__device__ __host__ __forceinline__ int pk(int c) {
    return (c & ~7) | ((c & 3) << 1) | ((c >> 2) & 1);
}

__device__ __forceinline__ float tfs(float f) {
    unsigned r;
    asm("cvt.rna.tf32.f32 %0, %1;" : "=r"(r) : "f"(f));
    return __uint_as_float(r);
}

__device__ __forceinline__ void mma8(float* c, float a0, float a1, float a2, float a3,
                                     float b0, float b1) {
    asm volatile(
        "mma.sync.aligned.m16n8k8.row.col.f32.tf32.tf32.f32 "
        "{%0,%1,%2,%3}, {%4,%5,%6,%7}, {%8,%9}, {%0,%1,%2,%3};"
        : "+f"(c[0]), "+f"(c[1]), "+f"(c[2]), "+f"(c[3])
        : "r"(__float_as_uint(a0)), "r"(__float_as_uint(a1)),
          "r"(__float_as_uint(a2)), "r"(__float_as_uint(a3)),
          "r"(__float_as_uint(b0)), "r"(__float_as_uint(b1)));
}

// ---------------- prepack kernels ------------------------------------------
__global__ void prepack_w(const float* __restrict__ qkv_w,
                          const float* __restrict__ proj_w) {
    int t = blockIdx.x * blockDim.x + threadIdx.x;
    if (t < TC3 * CDIM) {
        int n = t % TC3, k = t / TC3;
        g_wqkv_t[n * CDIM + pk(k)] = tfs(qkv_w[k * TC3 + n]);
    } else {
        int t2 = t - TC3 * CDIM;
        if (t2 < CDIM * CDIM) {
            int n = t2 % CDIM, k = t2 / CDIM;
            g_wproj_t[n * CDIM + pk(k)] = tfs(proj_w[k * CDIM + n]);
        }
    }
}

__global__ void prepack_rm(const float* __restrict__ mask,
                           const float* __restrict__ bias_t, int nmask) {
    int t = blockIdx.x * blockDim.x + threadIdx.x;
    int total = nmask * NHEAD * 64 * 64;
    if (t >= total) return;
    int j = t & 63;
    int i = (t >> 6) & 63;
    int h = (t >> 12) & (NHEAD - 1);
    int v = t >> 14;
    float val = -1.0e30f;
    if (i < NTOK && j < NTOK) {
        int ri = i / 7, ci = i - ri * 7;
        int rj = j / 7, cj = j - rj * 7;
        int idx = (ri - rj + 6) * 13 + (ci - cj + 6);
        val = bias_t[idx * NHEAD + h] + mask[(size_t)v * NTOK * NTOK + i * NTOK + j];
    }
    g_rm[t] = val;
}

// ---------------- main kernel ---------------------------------------------
__global__ __launch_bounds__(1024, 1) void win_attn_kernel(
    const float* __restrict__ x,      const float* __restrict__ qkv_b,
    const float* __restrict__ proj_b, float* __restrict__ out, int nmask)
{
    extern __shared__ float sm[];
    float* Qb = sm + OFF_Q;
    float* Kb = sm + OFF_K;
    float* VT = sm + OFF_VT;
    float* XS = sm + OFF_XS;
    float* WB = sm + OFF_WB;

    const int w    = blockIdx.x;
    const int tid  = threadIdx.x;
    const int warp = tid >> 5;
    const int lane = tid & 31;
    const int g    = lane >> 2;
    const int tig  = lane & 3;
    const int tg2  = tig * 2;

    const int mt  = warp & 3;        // GEMM1/4 M tile
    const int ngg = warp >> 2;       // GEMM1 n-tile (0..7) / GEMM4 n-group
    const int rb  = mt * 16;

    // ---------------- phase 0 ----------------------------------------------
    {
        const float* xg = x + (size_t)w * NTOK * CDIM;
        if (tid < NTOK * 16) {
            int r = tid >> 4, gb = (tid & 15) * 8;
            float4 v0 = *(const float4*)(xg + r * CDIM + gb);
            float4 v1 = *(const float4*)(xg + r * CDIM + gb + 4);
            float* d = XS + r * S136 + gb;
            *(float4*)(d)     = make_float4(tfs(v0.x), tfs(v1.x), tfs(v0.y), tfs(v1.y));
            *(float4*)(d + 4) = make_float4(tfs(v0.z), tfs(v1.z), tfs(v0.w), tfs(v1.w));
        }
        for (int u = tid; u < 15 * S136; u += 1024)      // XS pad rows = 0
            XS[NTOK * S136 + u] = 0.0f;
        if (tid < CDIM * 8) {                            // VT pad tokens 48..55 = 0
            int ch = tid >> 3, t = 48 + (tid & 7);
            VT[ch * SVT + pk(t)] = 0.0f;                 // t=48 overwritten later
        }
    }
    // prefetch + store W stage 0
    const float4* wsrc = (const float4*)g_wqkv_t;
    float4 pf[2];
    pf[0] = wsrc[tid];
    pf[1] = wsrc[1024 + tid];
    {
        int i0 = tid, i1 = 1024 + tid;
        *(float4*)(WB + (i0 >> 5) * S136 + (i0 & 31) * 4) = pf[0];
        *(float4*)(WB + (i1 >> 5) * S136 + (i1 & 31) * 4) = pf[1];
    }
    __syncthreads();

    // ---------------- GEMM1: 6 ping-pong stages of 64 n --------------------
    const float scale = 0.17677669529663687f;
#pragma unroll
    for (int s = 0; s < 6; s++) {
        float* buf  = WB + (s & 1) * (64 * S136);
        float* nbuf = WB + ((s + 1) & 1) * (64 * S136);
        if (s < 5) {
            pf[0] = wsrc[(s + 1) * 2048 + tid];
            pf[1] = wsrc[(s + 1) * 2048 + 1024 + tid];
        }
        float acc[4] = {0.f, 0.f, 0.f, 0.f};
#pragma unroll 4
        for (int kk = 0; kk < 16; kk++) {
            const int kc = kk * 8;
            float2 aA = *(float2*)(XS + (rb + g)     * S136 + kc + tg2);
            float2 aB = *(float2*)(XS + (rb + g + 8) * S136 + kc + tg2);
            float2 b  = *(float2*)(buf + (ngg * 8 + g) * S136 + kc + tg2);
            mma8(acc, aA.x, aB.x, aA.y, aB.y, b.x, b.y);
        }
        {
            const int cl = ngg * 8 + tg2;          // col within stage (0..63)
            const int gn = s * 64 + cl;
            const int c0 = (s & 1) * 64 + cl;      // col within Q/K/V (0..127)
            const float bb0 = qkv_b[gn], bb1 = qkv_b[gn + 1];
            const int r0 = rb + g, r1 = rb + g + 8;
            float v00 = acc[0] + bb0, v01 = acc[1] + bb1;
            float v10 = acc[2] + bb0, v11 = acc[3] + bb1;
            if (s < 2) {
                Qb[r0 * S136 + pk(c0)]     = tfs(v00 * scale);
                Qb[r0 * S136 + pk(c0 + 1)] = tfs(v01 * scale);
                Qb[r1 * S136 + pk(c0)]     = tfs(v10 * scale);
                Qb[r1 * S136 + pk(c0 + 1)] = tfs(v11 * scale);
            } else if (s < 4) {
                Kb[r0 * S136 + pk(c0)]     = tfs(v00);
                Kb[r0 * S136 + pk(c0 + 1)] = tfs(v01);
                Kb[r1 * S136 + pk(c0)]     = tfs(v10);
                Kb[r1 * S136 + pk(c0 + 1)] = tfs(v11);
            } else {
                if (r0 < NTOK) {
                    VT[c0 * SVT + pk(r0)]       = tfs(v00);
                    VT[(c0 + 1) * SVT + pk(r0)] = tfs(v01);
                }
                if (r1 < NTOK) {
                    VT[c0 * SVT + pk(r1)]       = tfs(v10);
                    VT[(c0 + 1) * SVT + pk(r1)] = tfs(v11);
                }
            }
        }
        if (s < 5) {
            int i0 = tid, i1 = 1024 + tid;
            *(float4*)(nbuf + (i0 >> 5) * S136 + (i0 & 31) * 4) = pf[0];
            *(float4*)(nbuf + (i1 >> 5) * S136 + (i1 & 31) * 4) = pf[1];
        }
        __syncthreads();
    }

    // ---------------- attention (warps 0-15) / proj prefetch (16-31) -------
    float4 pfj[8];
    if (warp < 16) {
        const int h   = warp >> 2;
        const int mt2 = warp & 3;
        const int rb2 = mt2 * 16;
        float* Pw = WB + warp * (16 * SP);     // per-warp P scratch

        // GEMM2: logits [16][64] in regs
        float lv[8][4];
#pragma unroll
        for (int t = 0; t < 8; t++) lv[t][0] = lv[t][1] = lv[t][2] = lv[t][3] = 0.f;
#pragma unroll
        for (int kk = 0; kk < 4; kk++) {
            const int kc = h * 32 + kk * 8;
            float2 aA = *(float2*)(Qb + (rb2 + g)     * S136 + kc + tg2);
            float2 aB = *(float2*)(Qb + (rb2 + g + 8) * S136 + kc + tg2);
#pragma unroll
            for (int t = 0; t < 8; t++) {
                float2 b = *(float2*)(Kb + (t * 8 + g) * S136 + kc + tg2);
                mma8(lv[t], aA.x, aB.x, aA.y, aB.y, b.x, b.y);
            }
        }
        // + rpb+mask (padded table, no predicates), softmax in regs
        {
            const int v = w % nmask;
            const float* rm0 = g_rm + ((size_t)((v * NHEAD + h) * 64 + rb2 + g)) * 64;
            const float* rm1 = rm0 + 8 * 64;
            float mx0 = -3.0e38f, mx1 = -3.0e38f;
#pragma unroll
            for (int t = 0; t < 8; t++) {
                const int j0 = t * 8 + tg2;
                float2 r0 = *(const float2*)(rm0 + j0);
                float2 r1 = *(const float2*)(rm1 + j0);
                lv[t][0] += r0.x; lv[t][1] += r0.y;
                lv[t][2] += r1.x; lv[t][3] += r1.y;
                mx0 = fmaxf(mx0, fmaxf(lv[t][0], lv[t][1]));
                mx1 = fmaxf(mx1, fmaxf(lv[t][2], lv[t][3]));
            }
            mx0 = fmaxf(mx0, __shfl_xor_sync(0xffffffffu, mx0, 1));
            mx0 = fmaxf(mx0, __shfl_xor_sync(0xffffffffu, mx0, 2));
            mx1 = fmaxf(mx1, __shfl_xor_sync(0xffffffffu, mx1, 1));
            mx1 = fmaxf(mx1, __shfl_xor_sync(0xffffffffu, mx1, 2));
            float s0 = 0.f, s1 = 0.f;
#pragma unroll
            for (int t = 0; t < 8; t++) {
                lv[t][0] = __expf(lv[t][0] - mx0);
                lv[t][1] = __expf(lv[t][1] - mx0);
                lv[t][2] = __expf(lv[t][2] - mx1);
                lv[t][3] = __expf(lv[t][3] - mx1);
                s0 += lv[t][0] + lv[t][1];
                s1 += lv[t][2] + lv[t][3];
            }
            s0 += __shfl_xor_sync(0xffffffffu, s0, 1);
            s0 += __shfl_xor_sync(0xffffffffu, s0, 2);
            s1 += __shfl_xor_sync(0xffffffffu, s1, 1);
            s1 += __shfl_xor_sync(0xffffffffu, s1, 2);
            const float inv0 = 1.0f / s0, inv1 = 1.0f / s1;

            // store unnormalized P (tf32), pk on token dim (tokens 0..55)
            const int pa = pk(tg2), pb = pk(tg2 + 1);
#pragma unroll
            for (int t = 0; t < 7; t++) {
                Pw[g * SP + t * 8 + pa]       = tfs(lv[t][0]);
                Pw[g * SP + t * 8 + pb]       = tfs(lv[t][1]);
                Pw[(g + 8) * SP + t * 8 + pa] = tfs(lv[t][2]);
                Pw[(g + 8) * SP + t * 8 + pb] = tfs(lv[t][3]);
            }
            __syncwarp();

            // GEMM3: ao [16][32] = P [16][56] @ V_h^T
            float a3[4][4];
#pragma unroll
            for (int t = 0; t < 4; t++) a3[t][0] = a3[t][1] = a3[t][2] = a3[t][3] = 0.f;
#pragma unroll
            for (int kk = 0; kk < 7; kk++) {
                const int kc = kk * 8;
                float2 aA = *(float2*)(Pw + g       * SP + kc + tg2);
                float2 aB = *(float2*)(Pw + (g + 8) * SP + kc + tg2);
#pragma unroll
                for (int t = 0; t < 4; t++) {
                    float2 b = *(float2*)(VT + (h * 32 + t * 8 + g) * SVT + kc + tg2);
                    mma8(a3[t], aA.x, aB.x, aA.y, aB.y, b.x, b.y);
                }
            }
            // normalize + store attn-out (packed A for GEMM4)
#pragma unroll
            for (int t = 0; t < 4; t++) {
                const int c0 = h * 32 + t * 8 + tg2;
                XS[(rb2 + g)     * S136 + pk(c0)]     = tfs(a3[t][0] * inv0);
                XS[(rb2 + g)     * S136 + pk(c0 + 1)] = tfs(a3[t][1] * inv0);
                XS[(rb2 + g + 8) * S136 + pk(c0)]     = tfs(a3[t][2] * inv1);
                XS[(rb2 + g + 8) * S136 + pk(c0 + 1)] = tfs(a3[t][3] * inv1);
            }
        }
    } else {
        const float4* psrc = (const float4*)g_wproj_t;
        const int t2 = tid - 512;
#pragma unroll
        for (int u = 0; u < 8; u++) pfj[u] = psrc[u * 512 + t2];
    }
    __syncthreads();

    if (warp >= 16) {
        const int t2 = tid - 512;
#pragma unroll
        for (int u = 0; u < 8; u++) {
            int idx = u * 512 + t2;
            *(float4*)(WB + (idx >> 5) * S136 + (idx & 31) * 4) = pfj[u];
        }
    }
    __syncthreads();

    // ---------------- GEMM4: y[64,128] = ao @ proj_w + b, direct STG -------
    {
        float acc[2][4];
#pragma unroll
        for (int t = 0; t < 2; t++) acc[t][0] = acc[t][1] = acc[t][2] = acc[t][3] = 0.f;
#pragma unroll 4
        for (int kk = 0; kk < 16; kk++) {
            const int kc = kk * 8;
            float2 aA = *(float2*)(XS + (rb + g)     * S136 + kc + tg2);
            float2 aB = *(float2*)(XS + (rb + g + 8) * S136 + kc + tg2);
#pragma unroll
            for (int t = 0; t < 2; t++) {
                float2 b = *(float2*)(WB + (ngg * 16 + t * 8 + g) * S136 + kc + tg2);
                mma8(acc[t], aA.x, aB.x, aA.y, aB.y, b.x, b.y);
            }
        }
        float* og = out + (size_t)w * NTOK * CDIM;
        const int r0 = rb + g, r1 = rb + g + 8;
#pragma unroll
        for (int t = 0; t < 2; t++) {
            const int c0 = ngg * 16 + t * 8 + tg2;
            const float b0 = proj_b[c0], b1 = proj_b[c0 + 1];
            if (r0 < NTOK)
                *(float2*)(og + r0 * CDIM + c0) = make_float2(acc[t][0] + b0, acc[t][1] + b1);
            if (r1 < NTOK)
                *(float2*)(og + r1 * CDIM + c0) = make_float2(acc[t][2] + b0, acc[t][3] + b1);
        }
    }
}

extern "C" void kernel_launch(void* const* d_in, const int* in_sizes, int n_in,
                              void* d_out, int out_size) {
    const float* x      = (const float*)d_in[0];
    const float* qkv_w  = (const float*)d_in[1];
    const float* qkv_b  = (const float*)d_in[2];
    const float* proj_w = (const float*)d_in[3];
    const float* proj_b = (const float*)d_in[4];
    const float* bias_t = (const float*)d_in[5];
    const float* mask   = (const float*)d_in[6];
    float* out = (float*)d_out;

    const int bw    = in_sizes[0] / (NTOK * CDIM);   // 4096
    const int nmask = in_sizes[6] / (NTOK * NTOK);   // 64

    prepack_w<<<(TC3 * CDIM + CDIM * CDIM + 255) / 256, 256>>>(qkv_w, proj_w);
    {
        int total = nmask * NHEAD * 64 * 64;
        prepack_rm<<<(total + 255) / 256, 256>>>(mask, bias_t, nmask);
    }

    const size_t smem = SMEMF * sizeof(float);       // 215040 B
    cudaFuncSetAttribute(win_attn_kernel,
                         cudaFuncAttributeMaxDynamicSharedMemorySize, (int)smem);
    win_attn_kernel<<<bw, 1024, smem>>>(x, qkv_b, proj_b, out, nmask);
}